// round 5
// baseline (speedup 1.0000x reference)
#include <cuda_runtime.h>
#include <cuda_bf16.h>
#include <math.h>

// Problem constants
#define T_STEPS 4
#define BATCH   32
#define CIN     64
#define COUT    64
#define NLEN    4096
#define KS      8
#define NSAMP   (T_STEPS * BATCH)          // 128 "samples" for the conv
#define CIK     (CIN * KS)                 // 512
#define CNT_D   524288.0                   // NSAMP * NLEN per-channel BN count

// Conv tiling
#define TN      256                        // n-tile per CTA
#define NTILES  (NLEN / TN)                // 16
#define XHALO   (TN + KS)                  // 264 floats per ci row in smem
#define SMEM_W  (CIK * COUT)               // 32768 floats
#define SMEM_X  (CIN * XHALO)              // 16896 floats
#define SMEM_BYTES ((SMEM_W + SMEM_X) * 4) // 198656 B dynamic smem

// Scratch (static device allocations are the sanctioned workaround)
__device__ __align__(16) float  g_y[(size_t)NSAMP * COUT * NLEN]; // 128 MB conv output
__device__ __align__(16) float  g_wT[SMEM_W];                     // transposed weights [cik][co]
__device__ double g_sum[COUT];
__device__ double g_sumsq[COUT];
__device__ float  g_scale[COUT];
__device__ float  g_shift[COUT];

// ---------------------------------------------------------------------------
// Kernel 0: transpose weights [co][ci][k] -> [cik][co], zero the stat buffers.
// ---------------------------------------------------------------------------
__global__ void wprep_kernel(const float* __restrict__ w)
{
    int i = blockIdx.x * blockDim.x + threadIdx.x;   // 0 .. 32767
    int co  = i >> 9;          // / 512
    int cik = i & 511;
    g_wT[cik * COUT + co] = w[i];
    if (i < COUT) {
        g_sum[i]   = 0.0;
        g_sumsq[i] = 0.0;
    }
}

// ---------------------------------------------------------------------------
// Kernel 1: conv (no bias - BN removes it), write y, accumulate BN stats.
// Grid: (NTILES, NSAMP), 256 threads.
// Thread tile: 8 co (as 4 co-pairs, packed f32x2) x 8 n (stride 32).
// ---------------------------------------------------------------------------
__global__ void __launch_bounds__(256, 1)
conv_kernel(const float* __restrict__ x)
{
    extern __shared__ float smem[];
    float* w_s = smem;             // [cik][co]    32768 floats
    float* x_s = smem + SMEM_W;    // [ci][XHALO]  16896 floats

    const int tid = threadIdx.x;
    const int s   = blockIdx.y;            // sample (t*B+b), 0..127
    const int n0  = blockIdx.x * TN;

    // --- stage weights (coalesced, already transposed) ---
    {
        float4*       ws4 = reinterpret_cast<float4*>(w_s);
        const float4* wg4 = reinterpret_cast<const float4*>(g_wT);
        #pragma unroll
        for (int i = tid; i < SMEM_W / 4; i += 256) ws4[i] = wg4[i];
    }
    // --- stage x tile with left-3 / right-4 zero halo ---
    {
        const float* xg = x + (size_t)s * (CIN * NLEN);
        for (int e = tid; e < CIN * XHALO; e += 256) {
            int ci = e / XHALO;
            int i  = e - ci * XHALO;
            int n  = n0 - 3 + i;
            x_s[e] = (n >= 0 && n < NLEN) ? xg[ci * NLEN + n] : 0.0f;
        }
    }
    __syncthreads();

    const int tn = tid & 31;   // n lane
    const int tw = tid >> 5;   // co group (warp id), co rows [tw*8, tw*8+8)

    unsigned long long acc[4][8] = {};   // [co-pair][j], f32x2 packed

    const float* wsp = w_s + tw * 8;     // co offset
    const float* xsp = x_s + tn;

    #pragma unroll 2
    for (int ci = 0; ci < CIN; ++ci) {
        const float* xr = xsp + ci * XHALO;
        const float* wr = wsp + ci * (KS * COUT);
        #pragma unroll
        for (int k = 0; k < KS; ++k) {
            unsigned long long w2[4];
            #pragma unroll
            for (int p = 0; p < 4; ++p)
                w2[p] = *reinterpret_cast<const unsigned long long*>(wr + k * COUT + 2 * p);
            #pragma unroll
            for (int j = 0; j < 8; ++j) {
                float xv = xr[k + 32 * j];
                unsigned long long x2;
                asm("mov.b64 %0, {%1, %1};" : "=l"(x2) : "f"(xv));
                #pragma unroll
                for (int p = 0; p < 4; ++p)
                    asm("fma.rn.f32x2 %0, %1, %2, %0;"
                        : "+l"(acc[p][j]) : "l"(w2[p]), "l"(x2));
            }
        }
    }

    // --- epilogue: store y + per-channel stat reduction ---
    float* yout = g_y + (size_t)s * (COUT * NLEN) + n0 + tn;

    #pragma unroll
    for (int p = 0; p < 4; ++p) {
        const int co = tw * 8 + 2 * p;
        float slo = 0.f, qlo = 0.f, shi = 0.f, qhi = 0.f;
        #pragma unroll
        for (int j = 0; j < 8; ++j) {
            unsigned long long a = acc[p][j];
            float lo = __uint_as_float((unsigned)(a));
            float hi = __uint_as_float((unsigned)(a >> 32));
            yout[(size_t)co * NLEN + 32 * j]       = lo;
            yout[(size_t)(co + 1) * NLEN + 32 * j] = hi;
            slo += lo; qlo += lo * lo;
            shi += hi; qhi += hi * hi;
        }
        #pragma unroll
        for (int off = 16; off; off >>= 1) {
            slo += __shfl_xor_sync(0xffffffffu, slo, off);
            qlo += __shfl_xor_sync(0xffffffffu, qlo, off);
            shi += __shfl_xor_sync(0xffffffffu, shi, off);
            qhi += __shfl_xor_sync(0xffffffffu, qhi, off);
        }
        if (tn == 0) {
            atomicAdd(&g_sum[co],       (double)slo);
            atomicAdd(&g_sumsq[co],     (double)qlo);
            atomicAdd(&g_sum[co + 1],   (double)shi);
            atomicAdd(&g_sumsq[co + 1], (double)qhi);
        }
    }
}

// ---------------------------------------------------------------------------
// Kernel 2: finalize BN affine per channel (bias cancels inside BN).
// ---------------------------------------------------------------------------
__global__ void bn_kernel(const float* __restrict__ gamma,
                          const float* __restrict__ beta)
{
    int c = threadIdx.x;
    if (c < COUT) {
        double m   = g_sum[c] / CNT_D;
        double var = g_sumsq[c] / CNT_D - m * m;
        double sc  = (double)gamma[c] / sqrt(var + 1e-5);
        g_scale[c] = (float)sc;
        g_shift[c] = (float)((double)beta[c] - m * sc);
    }
}

// ---------------------------------------------------------------------------
// Kernel 3: BN apply + LIF over T=4, float4-vectorized.
// v = v + (x - v)/2 ; s = (v >= 1) ; v = s ? 0 : v   (hard reset, detach)
// ---------------------------------------------------------------------------
__global__ void __launch_bounds__(256)
lif_kernel(float* __restrict__ out)
{
    const int t4 = blockIdx.x * 256 + threadIdx.x;   // 0 .. 2097151  ((b*64+c)*1024 + n4)
    const int c  = (t4 >> 10) & 63;
    const float sc = g_scale[c];
    const float sh = g_shift[c];

    const float4* yp = reinterpret_cast<const float4*>(g_y);
    float4*       op = reinterpret_cast<float4*>(out);
    const int S4 = BATCH * COUT * (NLEN / 4);        // per-timestep stride in float4

    float vx = 0.f, vy = 0.f, vz = 0.f, vw = 0.f;
    #pragma unroll
    for (int t = 0; t < T_STEPS; ++t) {
        float4 a = yp[t4 + t * S4];
        float x0 = a.x * sc + sh;
        float x1 = a.y * sc + sh;
        float x2 = a.z * sc + sh;
        float x3 = a.w * sc + sh;
        vx = vx + (x0 - vx) * 0.5f;
        vy = vy + (x1 - vy) * 0.5f;
        vz = vz + (x2 - vz) * 0.5f;
        vw = vw + (x3 - vw) * 0.5f;
        float4 o;
        o.x = (vx >= 1.0f) ? 1.0f : 0.0f;
        o.y = (vy >= 1.0f) ? 1.0f : 0.0f;
        o.z = (vz >= 1.0f) ? 1.0f : 0.0f;
        o.w = (vw >= 1.0f) ? 1.0f : 0.0f;
        vx = (vx >= 1.0f) ? 0.0f : vx;
        vy = (vy >= 1.0f) ? 0.0f : vy;
        vz = (vz >= 1.0f) ? 0.0f : vz;
        vw = (vw >= 1.0f) ? 0.0f : vw;
        op[t4 + t * S4] = o;
    }
}

// ---------------------------------------------------------------------------
extern "C" void kernel_launch(void* const* d_in, const int* in_sizes, int n_in,
                              void* d_out, int out_size)
{
    const float* x     = (const float*)d_in[0];  // [4,32,64,4096]
    const float* w     = (const float*)d_in[1];  // [64,64,8]
    // d_in[2] = conv bias (cancels in BN), d_in[3] = gamma, d_in[4] = beta
    const float* gamma = (const float*)d_in[3];
    const float* beta  = (const float*)d_in[4];
    float* out = (float*)d_out;

    cudaFuncSetAttribute(conv_kernel,
                         cudaFuncAttributeMaxDynamicSharedMemorySize, SMEM_BYTES);

    wprep_kernel<<<128, 256>>>(w);
    conv_kernel<<<dim3(NTILES, NSAMP), 256, SMEM_BYTES>>>(x);
    bn_kernel<<<1, 64>>>(gamma, beta);
    lif_kernel<<<(BATCH * COUT * NLEN / 4) / 256, 256>>>(out);
}